// round 4
// baseline (speedup 1.0000x reference)
#include <cuda_runtime.h>

// ---------------------------------------------------------------------------
// Photonic Clements mesh, N=128. State = 256x128 complex; every reference
// matrix acts on the ROW index only (diagonal phases / 2x2 block mixers),
// so the 128 columns are independent.
//
// Mapping: block = column c; thread t (0..127) owns row pair (2t, 2t+1)
// as complex registers a (even row) and b (odd row).
//
// ROUND 4 change: complex OUTPUT SERIALIZATION branch on out_size.
//   out_size == 16384 -> harness cast complex64 -> float32 (REAL PART ONLY)
//   else              -> PLANAR float32: real plane [0:16384), imag [16384:32768)
// (interleaved re/im was written in rounds 1-3 and is falsified for both sizes)
// ---------------------------------------------------------------------------

#define NCOLS   128
#define NLAYERS 255

#define AM_  0.97467943448089633f    // sqrt(1-0.05)
#define PP_  0.71063352017759484f    // sqrt(0.5+0.005)
#define QQ_  0.70356236397351441f    // sqrt(0.5-0.005)
#define AMP_ (AM_*PP_)
#define AMQ_ (AM_*QQ_)
#define AX_  0.98994949366116653f    // sqrt(1-0.02)
#define XC_  (AX_*0.1f)                       // aX*sqrt(CT)
#define XS_  (AX_*0.99498743710661995f)       // aX*sqrt(1-CT), also corner scalar

__device__ float2 g_phase[NLAYERS * NCOLS];

__global__ void phase_kernel(const float* __restrict__ theta_even) {
    int i = blockIdx.x * blockDim.x + threadIdx.x;
    if (i < NLAYERS * NCOLS) {
        float s, c;
        sincosf(theta_even[i], &s, &c);
        g_phase[i] = make_float2(c, s);
    }
}

__device__ __forceinline__ float2 cmul(float2 v, float c, float s) {
    return make_float2(fmaf(v.x, c, -v.y * s), fmaf(v.x, s, v.y * c));
}

__global__ void __launch_bounds__(128, 1)
mesh_kernel(const float* __restrict__ theta_in,
            const float* __restrict__ theta_out,
            float* __restrict__ out,
            int mode)   // 1 = real-only (16384 floats), 2 = planar (32768 floats)
{
    __shared__ float2 sa[2][NCOLS];
    __shared__ float2 sb[2][NCOLS];

    const int c = blockIdx.x;    // column (input port)
    const int t = threadIdx.x;   // row pair (2t, 2t+1)

    // --- input: column c of MMI_IN @ diag(e^{i th_in}) ---
    float2 a = make_float2(0.f, 0.f);
    float2 b = make_float2(0.f, 0.f);
    if (t == c) {
        float s, co;
        sincosf(theta_in[c], &s, &co);
        a = make_float2(AMP_ * co,  AMP_ * s);
        b = make_float2(-AMQ_ * s,  AMQ_ * co);
    }

    int xp = 0;

    auto mixM = [&]() {   // MMI 2x2: a' = A a + iB b ; b' = iB a + A b
        float ar = fmaf(AMP_, a.x, -AMQ_ * b.y);
        float ai = fmaf(AMP_, a.y,  AMQ_ * b.x);
        float br = fmaf(AMP_, b.x, -AMQ_ * a.y);
        float bi = fmaf(AMP_, b.y,  AMQ_ * a.x);
        a.x = ar; a.y = ai; b.x = br; b.y = bi;
    };

    auto crossX = [&]() {
        sa[xp][t] = a;
        sb[xp][t] = b;
        __syncthreads();
        float2 an = sa[xp][(t < NCOLS - 1) ? t + 1 : t];  // a_{t+1}
        float2 bp = sb[xp][(t > 0) ? t - 1 : t];          // b_{t-1}
        float2 na, nb;
        nb.x = fmaf(XC_, b.x, -XS_ * an.y);
        nb.y = fmaf(XC_, b.y,  XS_ * an.x);
        na.x = fmaf(XC_, a.x, -XS_ * bp.y);
        na.y = fmaf(XC_, a.y,  XS_ * bp.x);
        if (t == 0)         { na.x = XS_ * a.x; na.y = XS_ * a.y; }
        if (t == NCOLS - 1) { nb.x = XS_ * b.x; nb.y = XS_ * b.y; }
        a = na; b = nb;
        xp ^= 1;
    };

    // --- D0, M, X ---
    {
        float2 p = g_phase[0 * NCOLS + t];
        a = cmul(a, p.x, p.y);
        mixM();
        crossX();
    }

    float2 pa = g_phase[1 * NCOLS + t];
    float2 pb = g_phase[2 * NCOLS + t];

#pragma unroll 1
    for (int k = 0; k < 126; k++) {
        float2 npa = g_phase[(3 + 2 * k) * NCOLS + t];
        float2 npb = g_phase[(4 + 2 * k) * NCOLS + t];
        a = cmul(a, pa.x, pa.y);
        mixM();
        a = cmul(a, pb.x, pb.y);
        mixM();
        crossX();
        pa = npa; pb = npb;
    }

    a = cmul(a, pa.x, pa.y);   // D253
    mixM();
    a = cmul(a, pb.x, pb.y);   // D254

    // --- out row t: MMI_OUT pair reduce, then e^{i th_out[t]} ---
    float ox = fmaf(AMP_, a.x, -AMQ_ * b.y);
    float oy = fmaf(AMP_, a.y,  AMQ_ * b.x);
    float s, co;
    sincosf(theta_out[t], &s, &co);
    float re = ox * co - oy * s;
    float im = ox * s + oy * co;

    if (mode == 1) {
        out[t * NCOLS + c] = re;                       // real part only
    } else {
        out[t * NCOLS + c]               = re;         // real plane
        out[NCOLS * NCOLS + t * NCOLS + c] = im;       // imag plane
    }
}

extern "C" void kernel_launch(void* const* d_in, const int* in_sizes, int n_in,
                              void* d_out, int out_size) {
    // Identify inputs by SIZE (theta_even is the unique 32640-elem array;
    // theta_in precedes theta_out in both dict and alphabetical order).
    const float* th_ev  = nullptr;
    const float* small_[2] = {nullptr, nullptr};
    int ns = 0;
    for (int i = 0; i < n_in && i < 3; i++) {
        if (in_sizes[i] > 1000) th_ev = (const float*)d_in[i];
        else if (ns < 2)        small_[ns++] = (const float*)d_in[i];
    }
    const float* th_in  = small_[0];
    const float* th_out = small_[1];

    int mode = (out_size == NCOLS * NCOLS) ? 1 : 2;  // 16384 -> real-only, else planar

    phase_kernel<<<(NLAYERS * NCOLS + 255) / 256, 256>>>(th_ev);
    mesh_kernel<<<NCOLS, NCOLS>>>(th_in, th_out, (float*)d_out, mode);
}

// round 5
// speedup vs baseline: 1.3454x; 1.3454x over previous
#include <cuda_runtime.h>

// ---------------------------------------------------------------------------
// Photonic Clements mesh, N=128. 256x128 complex state; columns independent.
//
// ROUND 5 mapping: ONE WARP PER COLUMN. Lane t owns rows 8t..8t+7 as named
// complex registers v0..v7. MMI pairs (v0,v1)(v2,v3)(v4,v5)(v6,v7) and CROSS
// interior pairs (v1,v2)(v3,v4)(v5,v6) are lane-local; the CROSS boundary
// (8t+7, 8t+8) uses 4 up-front shuffles, both sides computed redundantly.
// No __syncthreads, no shared memory. Distance-2 phase prefetch from L2.
// Output serialization identical to the passing round-4 kernel.
// ---------------------------------------------------------------------------

#define NCOLS   128
#define NLAYERS 255
#define FULL    0xffffffffu

#define AM_  0.97467943448089633f    // sqrt(1-0.05)
#define PP_  0.71063352017759484f    // sqrt(0.5+0.005)
#define QQ_  0.70356236397351441f    // sqrt(0.5-0.005)
#define AMP_ (AM_*PP_)
#define AMQ_ (AM_*QQ_)
#define AX_  0.98994949366116653f    // sqrt(1-0.02)
#define XC_  (AX_*0.1f)                       // aX*sqrt(CT)
#define XS_  (AX_*0.99498743710661995f)       // aX*sqrt(1-CT), also corner scalar

// phase table: layer k, lane t reads float4s [k*64 + 2t] and [k*64 + 2t + 1]
// (= phases for theta_even columns 4t..4t+3, stored as (cos,sin) float2 pairs)
__device__ float4 g_phase4[NLAYERS * 64];

__global__ void phase_kernel(const float* __restrict__ theta_even) {
    int i = blockIdx.x * blockDim.x + threadIdx.x;
    if (i < NLAYERS * NCOLS) {
        float s, c;
        sincosf(theta_even[i], &s, &c);
        reinterpret_cast<float2*>(g_phase4)[i] = make_float2(c, s);
    }
}

// v *= (c + i s)
#define CMUL(v, c_, s_) do { \
    float _nx = fmaf((v).x, (c_), -(v).y * (s_)); \
    float _ny = fmaf((v).x, (s_),  (v).y * (c_)); \
    (v).x = _nx; (v).y = _ny; } while (0)

// [a;b] <- [[A, iB],[iB, A]] [a;b]
#define MIX(a, b, A, B) do { \
    float _ar = fmaf((A), (a).x, -(B) * (b).y); \
    float _ai = fmaf((A), (a).y,  (B) * (b).x); \
    float _br = fmaf((A), (b).x, -(B) * (a).y); \
    float _bi = fmaf((A), (b).y,  (B) * (a).x); \
    (a).x = _ar; (a).y = _ai; (b).x = _br; (b).y = _bi; } while (0)

#define APPLY_D(p01, p23) do { \
    CMUL(v0, (p01).x, (p01).y); \
    CMUL(v2, (p01).z, (p01).w); \
    CMUL(v4, (p23).x, (p23).y); \
    CMUL(v6, (p23).z, (p23).w); } while (0)

#define APPLY_M() do { \
    MIX(v0, v1, AMP_, AMQ_); \
    MIX(v2, v3, AMP_, AMQ_); \
    MIX(v4, v5, AMP_, AMQ_); \
    MIX(v6, v7, AMP_, AMQ_); } while (0)

#define APPLY_X() do { \
    float _nb0x = __shfl_down_sync(FULL, v0.x, 1); /* lane t+1's v0 = row 8t+8 */ \
    float _nb0y = __shfl_down_sync(FULL, v0.y, 1); \
    float _nb7x = __shfl_up_sync  (FULL, v7.x, 1); /* lane t-1's v7 = row 8t-1 */ \
    float _nb7y = __shfl_up_sync  (FULL, v7.y, 1); \
    MIX(v1, v2, XC_, XS_); \
    MIX(v3, v4, XC_, XS_); \
    MIX(v5, v6, XC_, XS_); \
    float _n7x = fmaf(XC_, v7.x, -XS_ * _nb0y); \
    float _n7y = fmaf(XC_, v7.y,  XS_ * _nb0x); \
    float _n0x = fmaf(XC_, v0.x, -XS_ * _nb7y); \
    float _n0y = fmaf(XC_, v0.y,  XS_ * _nb7x); \
    v7.x = (t < 31) ? _n7x : XS_ * v7.x;   /* row 255 corner */ \
    v7.y = (t < 31) ? _n7y : XS_ * v7.y; \
    v0.x = (t > 0)  ? _n0x : XS_ * v0.x;   /* row 0 corner */ \
    v0.y = (t > 0)  ? _n0y : XS_ * v0.y; } while (0)

#define PH(k, h) g_phase4[(k) * 64 + 2 * t + (h)]

__global__ void __launch_bounds__(32, 1)
mesh_kernel(const float* __restrict__ theta_in,
            const float* __restrict__ theta_out,
            float* __restrict__ out,
            int mode)   // 1 = real-only (16384 floats), 2 = planar (32768 floats)
{
    const int c = blockIdx.x;    // column (input port)
    const int t = threadIdx.x;   // lane: rows 8t..8t+7

    float2 v0 = {0.f, 0.f}, v1 = {0.f, 0.f}, v2 = {0.f, 0.f}, v3 = {0.f, 0.f};
    float2 v4 = {0.f, 0.f}, v5 = {0.f, 0.f}, v6 = {0.f, 0.f}, v7 = {0.f, 0.f};

    // --- input: column c of MMI_IN @ diag(e^{i th_in}) hits rows 2c, 2c+1 ---
    {
        float s, co;
        sincosf(theta_in[c], &s, &co);
        float2 ain = make_float2( AMP_ * co, AMP_ * s);   //  aM*p * e^{i th}
        float2 bin = make_float2(-AMQ_ * s,  AMQ_ * co);  // i*aM*q * e^{i th}
        int slot = 2 * c - 8 * t;   // even slot 0/2/4/6 if rows in this lane
        if      (slot == 0) { v0 = ain; v1 = bin; }
        else if (slot == 2) { v2 = ain; v3 = bin; }
        else if (slot == 4) { v4 = ain; v5 = bin; }
        else if (slot == 6) { v6 = ain; v7 = bin; }
    }

    // --- D0, M, X ---
    {
        float4 p01 = PH(0, 0), p23 = PH(0, 1);
        APPLY_D(p01, p23);
        APPLY_M();
        APPLY_X();
    }

    // Virtual iteration j (0..126) consumes layers 2j+1 (a) and 2j+2 (b).
    // j = 0..125: D,M,D,M,X.  j = 126: tail D253, M, D254.
    // Distance-2 double-buffered prefetch; unroll-2 keeps slots in registers.
    float4 s0a0 = PH(1, 0), s0a1 = PH(1, 1), s0b0 = PH(2, 0), s0b1 = PH(2, 1);
    float4 s1a0 = PH(3, 0), s1a1 = PH(3, 1), s1b0 = PH(4, 0), s1b1 = PH(4, 1);

#pragma unroll 1
    for (int j = 0; j < 126; j += 2) {
        {   // iteration j: uses slot 0, prefetches j+2 into slot 0
            int jn = (j + 2 <= 126) ? (j + 2) : 126;     // clamp (redundant load ok)
            float4 na0 = PH(2 * jn + 1, 0), na1 = PH(2 * jn + 1, 1);
            float4 nb0 = PH(2 * jn + 2, 0), nb1 = PH(2 * jn + 2, 1);
            APPLY_D(s0a0, s0a1);
            APPLY_M();
            APPLY_D(s0b0, s0b1);
            APPLY_M();
            APPLY_X();
            s0a0 = na0; s0a1 = na1; s0b0 = nb0; s0b1 = nb1;
        }
        {   // iteration j+1: uses slot 1, prefetches j+3 into slot 1
            int jn = (j + 3 <= 126) ? (j + 3) : 126;
            float4 na0 = PH(2 * jn + 1, 0), na1 = PH(2 * jn + 1, 1);
            float4 nb0 = PH(2 * jn + 2, 0), nb1 = PH(2 * jn + 2, 1);
            APPLY_D(s1a0, s1a1);
            APPLY_M();
            APPLY_D(s1b0, s1b1);
            APPLY_M();
            APPLY_X();
            s1a0 = na0; s1a1 = na1; s1b0 = nb0; s1b1 = nb1;
        }
    }

    // --- tail j=126: D253, M, D254 (slot 0 holds layers 253/254: loaded at j=124) ---
    APPLY_D(s0a0, s0a1);
    APPLY_M();
    APPLY_D(s0b0, s0b1);

    // --- output rows j = 4t..4t+3: MMI_OUT pair reduce, then e^{i th_out[j]} ---
#define OUTP(va, vb, jj) do { \
        float _ox = fmaf(AMP_, (va).x, -AMQ_ * (vb).y); \
        float _oy = fmaf(AMP_, (va).y,  AMQ_ * (vb).x); \
        float _so, _co; sincosf(theta_out[jj], &_so, &_co); \
        float _re = _ox * _co - _oy * _so; \
        float _im = _ox * _so + _oy * _co; \
        if (mode == 1) { out[(jj) * NCOLS + c] = _re; } \
        else { out[(jj) * NCOLS + c] = _re; \
               out[NCOLS * NCOLS + (jj) * NCOLS + c] = _im; } } while (0)

    OUTP(v0, v1, 4 * t);
    OUTP(v2, v3, 4 * t + 1);
    OUTP(v4, v5, 4 * t + 2);
    OUTP(v6, v7, 4 * t + 3);
#undef OUTP
}

extern "C" void kernel_launch(void* const* d_in, const int* in_sizes, int n_in,
                              void* d_out, int out_size) {
    // Inputs identified by SIZE (theta_even = unique 32640-elem array;
    // theta_in precedes theta_out).
    const float* th_ev  = nullptr;
    const float* small_[2] = {nullptr, nullptr};
    int ns = 0;
    for (int i = 0; i < n_in && i < 3; i++) {
        if (in_sizes[i] > 1000) th_ev = (const float*)d_in[i];
        else if (ns < 2)        small_[ns++] = (const float*)d_in[i];
    }
    const float* th_in  = small_[0];
    const float* th_out = small_[1];

    int mode = (out_size == NCOLS * NCOLS) ? 1 : 2;  // 16384 -> real-only, else planar

    phase_kernel<<<(NLAYERS * NCOLS + 255) / 256, 256>>>(th_ev);
    mesh_kernel<<<NCOLS, 32>>>(th_in, th_out, (float*)d_out, mode);
}